// round 5
// baseline (speedup 1.0000x reference)
#include <cuda_runtime.h>
#include <cuda_bf16.h>
#include <cstdint>

// ============================================================================
// BarrierNet — HMMA bf16 hi/lo (~fp32), swizzled smem, double-buffered A & B,
// 2 syncs/chunk, cp.async-pipelined B, fused epilogue + closed-form QP.
// ============================================================================

#define NTH        512

// smem byte offsets (all 1024-aligned)
//  A buffers: 2 x (hi 16384 + lo 16384) = 65536
//  B buffers: 2 x (hi 32768 + lo 32768) = 131072
#define ABUF(i)    ((i) * 32768)
#define A_LO       16384
#define BBUF(i)    (65536 + (i) * 65536)
#define B_LO       32768
#define XS_OFF     196608        // 128*8 f32 = 4096
#define B2_OFF     200704        // 256 f32
#define W3A_OFF    201728
#define W3B_OFF    202752
#define RED_OFF    203776        // 4 x 128 float2 = 4096
#define SMEM_TOTAL 207872

// prep image: [chunk4][plane2(hi,lo)][nc256][128B swizzled]  (65536 B / chunk)
__device__ __align__(16) unsigned char BIMG[262144];

__constant__ float OBX[8] = {
    10.0f, 7.0710678118654755f, 6.123233995736766e-16f, -7.0710678118654755f,
    -10.0f, -7.0710678118654755f, -1.8369701987210297e-15f, 7.0710678118654755f };
__constant__ float OBY[8] = {
    0.0f, 7.0710678118654755f, 10.0f, 7.0710678118654755f,
    1.2246467991473532e-15f, -7.0710678118654755f, -10.0f, -7.0710678118654755f };

// ---------------------------------------------------------------- asm helpers
__device__ __forceinline__ uint32_t smem_u32(const void* p) {
    uint32_t a;
    asm("{ .reg .u64 t; cvta.to.shared.u64 t, %1; cvt.u32.u64 %0, t; }"
        : "=r"(a) : "l"(p));
    return a;
}
__device__ __forceinline__ void mma16816(float* d, const uint32_t* a,
                                         uint32_t b0, uint32_t b1) {
    asm volatile(
        "mma.sync.aligned.m16n8k16.row.col.f32.bf16.bf16.f32 "
        "{%0,%1,%2,%3}, {%4,%5,%6,%7}, {%8,%9}, {%0,%1,%2,%3};"
        : "+f"(d[0]), "+f"(d[1]), "+f"(d[2]), "+f"(d[3])
        : "r"(a[0]), "r"(a[1]), "r"(a[2]), "r"(a[3]), "r"(b0), "r"(b1));
}
__device__ __forceinline__ void ldsm4(uint32_t* r, uint32_t addr) {
    asm volatile("ldmatrix.sync.aligned.m8n8.x4.shared.b16 {%0,%1,%2,%3}, [%4];"
                 : "=r"(r[0]), "=r"(r[1]), "=r"(r[2]), "=r"(r[3]) : "r"(addr));
}
#define CPASYNC16(dst, src) \
    asm volatile("cp.async.cg.shared.global [%0], [%1], 16;" \
                 :: "r"(dst), "l"(src))
#define CPCOMMIT() asm volatile("cp.async.commit_group;")
#define CPWAIT(n)  asm volatile("cp.async.wait_group %0;" :: "n"(n))

// ------------------------------------------------------------ QP (validated)
__device__ __forceinline__ float2 qp_solve(const float* f, float p0, float p1,
                                           float s0, float s1) {
    float px = f[0], py = f[1], th = f[2], v  = f[3];
    float ox = f[4], oy = f[5], ot = f[6], ov = f[7];
    float st = sinf(th), ct = cosf(th);
    float vs = v * st,  vc = v * ct;
    float ssum = s0 + s1, sprod = s0 * s1;

    float G0[9], G1[9], h[9];
    const float R2 = 0.8f * 0.8f;
    #pragma unroll
    for (int i = 0; i < 8; i++) {
        float dx = px - OBX[i], dy = py - OBY[i];
        float bar  = dx * dx + dy * dy - R2;
        float bdot = 2.0f * dx * vc + 2.0f * dy * vs;
        G0[i] = -(-2.0f * dx * vs + 2.0f * dy * vc);
        G1[i] = -( 2.0f * dx * ct + 2.0f * dy * st);
        h[i]  = 2.0f * v * v + ssum * bdot + sprod * bar;
    }
    {
        float dxo = px - ox, dyo = py - oy;
        float so = sinf(ot), co = cosf(ot);
        float bar  = dxo * dxo + dyo * dyo - 0.25f;
        float bdot = 2.0f * dxo * (vc - ov * co) + 2.0f * dyo * (vs - ov * so);
        float Lf2  = 2.0f * (v * v + ov * ov + 2.0f * v * ov * cosf(th - ot));
        G0[8] = -(-2.0f * dxo * vs + 2.0f * dyo * vc);
        G1[8] = -( 2.0f * dxo * ct + 2.0f * dyo * st);
        h[8]  = Lf2 + ssum * bdot + sprod * bar;
    }
    float tol[9];
    #pragma unroll
    for (int i = 0; i < 9; i++) tol[i] = h[i] + 1e-6f * (1.0f + fabsf(h[i]));

    float bz0 = -p0, bz1 = -p1;
    float bobj = 3.402823466e+38f;
    auto consider = [&](float zx, float zy) {
        bool feas = true;
        #pragma unroll
        for (int k = 0; k < 9; k++)
            feas = feas && (zx * G0[k] + zy * G1[k] <= tol[k]);
        float obj = 0.5f * (zx * zx + zy * zy) + zx * p0 + zy * p1;
        if (feas && obj < bobj) { bobj = obj; bz0 = zx; bz1 = zy; }
    };
    consider(-p0, -p1);
    #pragma unroll
    for (int i = 0; i < 9; i++) {
        float gg  = G0[i] * G0[i] + G1[i] * G1[i];
        float lam = (-(G0[i] * p0 + G1[i] * p1) - h[i]) / (gg + 1e-12f);
        if (lam >= -1e-8f) consider(-p0 - lam * G0[i], -p1 - lam * G1[i]);
    }
    for (int i = 0; i < 8; i++) {
        for (int j = i + 1; j < 9; j++) {
            float det = G0[i] * G1[j] - G1[i] * G0[j];
            if (fabsf(det) > 1e-9f) {
                float zx = (h[i] * G1[j] - h[j] * G1[i]) / det;
                float zy = (G0[i] * h[j] - G0[j] * h[i]) / det;
                float r0 = -(zx + p0), r1 = -(zy + p1);
                float li = (G1[j] * r0 - G0[j] * r1) / det;
                float lj = (G0[i] * r1 - G1[i] * r0) / det;
                if (li >= -1e-8f && lj >= -1e-8f) consider(zx, zy);
            }
        }
    }
    return make_float2(bz0, bz1);
}

// ---------------------------------- prep: W21/W22 -> swizzled bf16 hi/lo image
extern "C" __global__ void bnet_prep(const float* __restrict__ W21,
                                     const float* __restrict__ W22) {
    int idx = blockIdx.x * 256 + threadIdx.x;   // 65536 = 2br * 128n * 256k
    int br = idx >> 15;
    int n  = (idx >> 8) & 127;
    int k  = idx & 255;
    const float* W = br ? W22 : W21;
    float v = W[n * 256 + k];
    __nv_bfloat16 hi = __float2bfloat16(v);
    __nv_bfloat16 lo = __float2bfloat16(v - __bfloat162float(hi));
    int c  = k >> 6;
    int kk = k & 63;
    int nc = br * 128 + n;
    uint32_t inrow = (uint32_t)(kk * 2) ^ (uint32_t)((nc & 7) << 4);  // SW128
    size_t base = (size_t)c * 65536 + (size_t)nc * 128 + inrow;
    *(__nv_bfloat16*)(BIMG + base)         = hi;    // hi plane
    *(__nv_bfloat16*)(BIMG + base + 32768) = lo;    // lo plane
}

// ------------------------------------------------------------- main kernel
extern "C" __global__ void __launch_bounds__(NTH, 1)
bnet_main(const float* __restrict__ x,   const float* __restrict__ meanv,
          const float* __restrict__ stdv,
          const float* __restrict__ W1,  const float* __restrict__ b1,
          const float* __restrict__ b21v, const float* __restrict__ W31,
          const float* __restrict__ b31v,
          const float* __restrict__ b22v, const float* __restrict__ W32,
          const float* __restrict__ b32v,
          float* __restrict__ out, int Btot)
{
    extern __shared__ unsigned char sm[];
    const uint32_t smb = smem_u32(sm);
    const int tid  = threadIdx.x;
    const int wp   = tid >> 5;
    const int lane = tid & 31;
    const int g    = lane >> 2;
    const int t    = lane & 3;
    const int rg   = wp & 3;           // rows rg*32..+32
    const int cg   = wp >> 2;          // cols cg*64..+64
    const int row0 = blockIdx.x * 128;

    float* xs   = (float*)(sm + XS_OFF);
    float* b2s  = (float*)(sm + B2_OFF);
    float* w3a  = (float*)(sm + W3A_OFF);
    float* w3b  = (float*)(sm + W3B_OFF);
    float2* red = (float2*)(sm + RED_OFF);

    // ---- B prefetch: chunk0 -> BBUF0, chunk1 -> BBUF1 ----------------------
    auto fill_chunk = [&](uint32_t dstoff, int c) {
        const unsigned char* src = BIMG + (size_t)c * 65536;
        #pragma unroll
        for (int i = 0; i < 8; i++) {
            int idx = tid + i * NTH;
            CPASYNC16(smb + dstoff + idx * 16, src + idx * 16);
        }
    };
    fill_chunk(BBUF(0), 0); CPCOMMIT();
    fill_chunk(BBUF(1), 1); CPCOMMIT();

    // ---- small tensors + x-scale -------------------------------------------
    if (tid < 256) {
        b2s[tid] = (tid < 128) ? b21v[tid] : b22v[tid - 128];
        w3a[tid] = (tid < 128) ? W31[tid] : W32[tid - 128];
        w3b[tid] = (tid < 128) ? W31[128 + tid] : W32[tid];
    }
    for (int i = tid; i < 128 * 8; i += NTH) {
        int r = i >> 3, j = i & 7;
        int gr = row0 + r;
        float v = (gr < Btot) ? x[gr * 8 + j] : 0.0f;
        xs[i] = v * stdv[j] + meanv[j];
    }
    __syncthreads();    // xs ready

    // ---- phase-1 A-chunk compute (two units/thread, 8 rows/thread) ---------
    const int up = tid & 31;            // unit pair within chunk
    const int rq = tid >> 5;            // rows rq*8..+8
    auto computeA = [&](int c, uint32_t abuf) {
        int u0 = c * 64 + up * 2;
        const float4* w4 = (const float4*)(W1 + u0 * 8);
        float4 w0a = w4[0], w0b = w4[1], w1a = w4[2], w1b = w4[3];
        float bb0 = b1[u0], bb1 = b1[u0 + 1];
        unsigned char* base = sm + abuf;
        #pragma unroll
        for (int i = 0; i < 8; i++) {
            int m = rq * 8 + i;
            float4 fa = *(const float4*)(xs + m * 8);
            float4 fb = *(const float4*)(xs + m * 8 + 4);
            float a0 = bb0, a1 = bb1;
            a0 = fmaf(fa.x, w0a.x, a0); a0 = fmaf(fa.y, w0a.y, a0);
            a0 = fmaf(fa.z, w0a.z, a0); a0 = fmaf(fa.w, w0a.w, a0);
            a0 = fmaf(fb.x, w0b.x, a0); a0 = fmaf(fb.y, w0b.y, a0);
            a0 = fmaf(fb.z, w0b.z, a0); a0 = fmaf(fb.w, w0b.w, a0);
            a1 = fmaf(fa.x, w1a.x, a1); a1 = fmaf(fa.y, w1a.y, a1);
            a1 = fmaf(fa.z, w1a.z, a1); a1 = fmaf(fa.w, w1a.w, a1);
            a1 = fmaf(fb.x, w1b.x, a1); a1 = fmaf(fb.y, w1b.y, a1);
            a1 = fmaf(fb.z, w1b.z, a1); a1 = fmaf(fb.w, w1b.w, a1);
            a0 = fmaxf(a0, 0.0f); a1 = fmaxf(a1, 0.0f);
            __nv_bfloat16 h0 = __float2bfloat16(a0);
            __nv_bfloat16 h1 = __float2bfloat16(a1);
            __nv_bfloat16 l0 = __float2bfloat16(a0 - __bfloat162float(h0));
            __nv_bfloat16 l1 = __float2bfloat16(a1 - __bfloat162float(h1));
            uint32_t hw = ((uint32_t)*(uint16_t*)&h1 << 16) | *(uint16_t*)&h0;
            uint32_t lw = ((uint32_t)*(uint16_t*)&l1 << 16) | *(uint16_t*)&l0;
            uint32_t off = (uint32_t)(m * 128 + up * 4) ^ (uint32_t)((m & 7) << 4);
            *(uint32_t*)(base + off)        = hw;
            *(uint32_t*)(base + A_LO + off) = lw;
        }
    };
    computeA(0, ABUF(0));
    CPWAIT(1);          // B chunk 0 arrived
    __syncthreads();

    // ---- fragment addressing (swizzled) -------------------------------------
    const int rowA  = rg * 32 + ((lane >> 3) & 1) * 8 + (lane & 7);
    const int halfA = (lane >> 4) * 16;
    const int xorA  = (rowA & 7) << 4;
    const int nB    = cg * 64 + ((lane >> 4) & 1) * 8 + (lane & 7);
    const int halfB = ((lane >> 3) & 1) * 16;
    const int xorB  = (lane & 7) << 4;

    float acc[2][8][4];
    #pragma unroll
    for (int mt = 0; mt < 2; mt++)
        #pragma unroll
        for (int nt = 0; nt < 8; nt++)
            #pragma unroll
            for (int e = 0; e < 4; e++) acc[mt][nt][e] = 0.0f;

    #pragma unroll
    for (int c = 0; c < 4; c++) {
        const uint32_t aB = smb + ABUF(c & 1) + rowA * 128;
        const uint32_t bB = smb + BBUF(c & 1) + nB * 128;

        // ---- uninterrupted MMA block: 56 LDSM + 96 HMMA ----
        #pragma unroll
        for (int k0 = 0; k0 < 64; k0 += 16) {
            const uint32_t kaHi = (uint32_t)((k0 * 2 + halfA) ^ xorA);
            const uint32_t kb   = (uint32_t)((k0 * 2 + halfB) ^ xorB);
            uint32_t ah[2][4], al[2][4], bh[4][4];
            #pragma unroll
            for (int mt = 0; mt < 2; mt++) {
                ldsm4(ah[mt], aB + mt * (16 * 128) + kaHi);
                ldsm4(al[mt], aB + mt * (16 * 128) + kaHi + A_LO);
            }
            #pragma unroll
            for (int pr = 0; pr < 4; pr++)
                ldsm4(bh[pr], bB + pr * (16 * 128) + kb);
            #pragma unroll
            for (int pr = 0; pr < 4; pr++)
                #pragma unroll
                for (int mt = 0; mt < 2; mt++) {
                    mma16816(acc[mt][2 * pr],     ah[mt], bh[pr][0], bh[pr][1]);
                    mma16816(acc[mt][2 * pr],     al[mt], bh[pr][0], bh[pr][1]);
                    mma16816(acc[mt][2 * pr + 1], ah[mt], bh[pr][2], bh[pr][3]);
                    mma16816(acc[mt][2 * pr + 1], al[mt], bh[pr][2], bh[pr][3]);
                }
        }
        #pragma unroll
        for (int k0 = 0; k0 < 64; k0 += 16) {
            const uint32_t kaHi = (uint32_t)((k0 * 2 + halfA) ^ xorA);
            const uint32_t kb   = (uint32_t)((k0 * 2 + halfB) ^ xorB);
            uint32_t ah[2][4], bl[4][4];
            #pragma unroll
            for (int mt = 0; mt < 2; mt++)
                ldsm4(ah[mt], aB + mt * (16 * 128) + kaHi);
            #pragma unroll
            for (int pr = 0; pr < 4; pr++)
                ldsm4(bl[pr], bB + pr * (16 * 128) + kb + B_LO);
            #pragma unroll
            for (int pr = 0; pr < 4; pr++)
                #pragma unroll
                for (int mt = 0; mt < 2; mt++) {
                    mma16816(acc[mt][2 * pr],     ah[mt], bl[pr][0], bl[pr][1]);
                    mma16816(acc[mt][2 * pr + 1], ah[mt], bl[pr][2], bl[pr][3]);
                }
        }

        if (c < 3) computeA(c + 1, ABUF((c + 1) & 1));
        __syncthreads();                       // all consumed B(c), wrote A(c+1)
        if (c < 2) { fill_chunk(BBUF(c & 1), c + 2); CPCOMMIT(); }
        if (c == 0 || c == 1) CPWAIT(1);       // B(c+1) arrived
        else if (c == 2)      CPWAIT(0);       // B(3) arrived
        if (c < 3) __syncthreads();            // visibility of B(c+1) + A(c+1)
    }
    __syncthreads();

    // ---- epilogue: relu+bias, project to 2 outs, reduce ----------------------
    {
        const int branch  = cg >> 1;
        const int colbase = branch * 128 + (cg & 1) * 64;
        float y0A[2] = {0, 0}, y1A[2] = {0, 0};
        float y0B[2] = {0, 0}, y1B[2] = {0, 0};
        #pragma unroll
        for (int mt = 0; mt < 2; mt++) {
            #pragma unroll
            for (int nt = 0; nt < 8; nt++) {
                int c0 = colbase + nt * 8 + t * 2;
                float w3a0 = w3a[c0], w3a1 = w3a[c0 + 1];
                float w3b0 = w3b[c0], w3b1 = w3b[c0 + 1];
                float bb0 = b2s[c0], bb1 = b2s[c0 + 1];
                float h0 = fmaxf(acc[mt][nt][0] + bb0, 0.0f);
                float h1 = fmaxf(acc[mt][nt][1] + bb1, 0.0f);
                float h2 = fmaxf(acc[mt][nt][2] + bb0, 0.0f);
                float h3 = fmaxf(acc[mt][nt][3] + bb1, 0.0f);
                y0A[mt] = fmaf(h0, w3a0, fmaf(h1, w3a1, y0A[mt]));
                y1A[mt] = fmaf(h0, w3b0, fmaf(h1, w3b1, y1A[mt]));
                y0B[mt] = fmaf(h2, w3a0, fmaf(h3, w3a1, y0B[mt]));
                y1B[mt] = fmaf(h2, w3b0, fmaf(h3, w3b1, y1B[mt]));
            }
        }
        #pragma unroll
        for (int mt = 0; mt < 2; mt++) {
            #pragma unroll
            for (int msk = 1; msk <= 2; msk <<= 1) {
                y0A[mt] += __shfl_xor_sync(0xFFFFFFFFu, y0A[mt], msk);
                y1A[mt] += __shfl_xor_sync(0xFFFFFFFFu, y1A[mt], msk);
                y0B[mt] += __shfl_xor_sync(0xFFFFFFFFu, y0B[mt], msk);
                y1B[mt] += __shfl_xor_sync(0xFFFFFFFFu, y1B[mt], msk);
            }
        }
        if (t == 0) {
            #pragma unroll
            for (int mt = 0; mt < 2; mt++) {
                int rA = rg * 32 + mt * 16 + g;
                red[cg * 128 + rA]     = make_float2(y0A[mt], y1A[mt]);
                red[cg * 128 + rA + 8] = make_float2(y0B[mt], y1B[mt]);
            }
        }
    }
    __syncthreads();

    if (tid < 128) {
        const int gr = row0 + tid;
        if (gr < Btot) {
            float2 a0 = red[tid],       a1 = red[128 + tid];
            float2 c0 = red[256 + tid], c1 = red[384 + tid];
            float p0 = a0.x + a1.x + b31v[0];
            float p1 = a0.y + a1.y + b31v[1];
            float q0 = c0.x + c1.x + b32v[0];
            float q1 = c0.y + c1.y + b32v[1];
            float s0 = 4.0f / (1.0f + expf(-q0));
            float s1 = 4.0f / (1.0f + expf(-q1));
            float2 z = qp_solve(&xs[tid * 8], p0, p1, s0, s1);
            *(float2*)(out + gr * 2) = z;
        }
    }
}

// ---------------------------------------------------------------- launcher
extern "C" void kernel_launch(void* const* d_in, const int* in_sizes, int n_in,
                              void* d_out, int out_size)
{
    const float* x     = (const float*)d_in[0];
    const float* meanv = (const float*)d_in[1];
    const float* stdv  = (const float*)d_in[2];
    const float* W1    = (const float*)d_in[3];
    const float* b1    = (const float*)d_in[4];
    const float* W21   = (const float*)d_in[5];
    const float* b21   = (const float*)d_in[6];
    const float* W31   = (const float*)d_in[7];
    const float* b31   = (const float*)d_in[8];
    const float* W22   = (const float*)d_in[9];
    const float* b22   = (const float*)d_in[10];
    const float* W32   = (const float*)d_in[11];
    const float* b32   = (const float*)d_in[12];
    float* out = (float*)d_out;

    const int Btot = in_sizes[0] / 8;
    const int grid = (Btot + 127) / 128;

    bnet_prep<<<256, 256>>>(W21, W22);

    cudaFuncSetAttribute(bnet_main, cudaFuncAttributeMaxDynamicSharedMemorySize,
                         SMEM_TOTAL);
    bnet_main<<<grid, NTH, SMEM_TOTAL>>>(x, meanv, stdv, W1, b1,
                                         b21, W31, b31, b22, W32, b32,
                                         out, Btot);
}

// round 6
// speedup vs baseline: 1.2328x; 1.2328x over previous
#include <cuda_runtime.h>
#include <cuda_bf16.h>
#include <cstdint>

// ============================================================================
// BarrierNet — HMMA bf16 hi/lo (~fp32), 256thr/64row CTAs, 2 CTAs/SM,
// double-buffered A, plane-staged cp.async B, fused epilogue + QP.
// ============================================================================

#define NTH        256
#define TB         64

// smem byte offsets
#define ABUF(i)    ((i) * 16384)      // 2 x (hi 8192 + lo 8192)
#define A_LO       8192
#define B_HI       32768              // 32768 B (256n x 64k bf16, swizzled)
#define B_LO       65536              // 32768 B
#define XS_OFF     98304              // 64*8 f32 = 2048
#define B2_OFF     100352             // 256 f32
#define W3A_OFF    101376
#define W3B_OFF    102400
#define RED_OFF    103424             // 4 x 64 float2 = 2048
#define SMEM_TOTAL 105472

// prep image: [chunk4][plane2(hi,lo)][nc256][128B swizzled]  (65536 B / chunk)
__device__ __align__(16) unsigned char BIMG[262144];

__constant__ float OBX[8] = {
    10.0f, 7.0710678118654755f, 6.123233995736766e-16f, -7.0710678118654755f,
    -10.0f, -7.0710678118654755f, -1.8369701987210297e-15f, 7.0710678118654755f };
__constant__ float OBY[8] = {
    0.0f, 7.0710678118654755f, 10.0f, 7.0710678118654755f,
    1.2246467991473532e-15f, -7.0710678118654755f, -10.0f, -7.0710678118654755f };

// ---------------------------------------------------------------- asm helpers
__device__ __forceinline__ uint32_t smem_u32(const void* p) {
    uint32_t a;
    asm("{ .reg .u64 t; cvta.to.shared.u64 t, %1; cvt.u32.u64 %0, t; }"
        : "=r"(a) : "l"(p));
    return a;
}
__device__ __forceinline__ void mma16816(float* d, const uint32_t* a,
                                         uint32_t b0, uint32_t b1) {
    asm volatile(
        "mma.sync.aligned.m16n8k16.row.col.f32.bf16.bf16.f32 "
        "{%0,%1,%2,%3}, {%4,%5,%6,%7}, {%8,%9}, {%0,%1,%2,%3};"
        : "+f"(d[0]), "+f"(d[1]), "+f"(d[2]), "+f"(d[3])
        : "r"(a[0]), "r"(a[1]), "r"(a[2]), "r"(a[3]), "r"(b0), "r"(b1));
}
__device__ __forceinline__ void ldsm4(uint32_t* r, uint32_t addr) {
    asm volatile("ldmatrix.sync.aligned.m8n8.x4.shared.b16 {%0,%1,%2,%3}, [%4];"
                 : "=r"(r[0]), "=r"(r[1]), "=r"(r[2]), "=r"(r[3]) : "r"(addr));
}
#define CPASYNC16(dst, src) \
    asm volatile("cp.async.cg.shared.global [%0], [%1], 16;" \
                 :: "r"(dst), "l"(src))
#define CPCOMMIT() asm volatile("cp.async.commit_group;")
#define CPWAIT(n)  asm volatile("cp.async.wait_group %0;" :: "n"(n))

// ------------------------------------------------------------ QP (validated)
__device__ __forceinline__ float2 qp_solve(const float* f, float p0, float p1,
                                           float s0, float s1) {
    float px = f[0], py = f[1], th = f[2], v  = f[3];
    float ox = f[4], oy = f[5], ot = f[6], ov = f[7];
    float st = sinf(th), ct = cosf(th);
    float vs = v * st,  vc = v * ct;
    float ssum = s0 + s1, sprod = s0 * s1;

    float G0[9], G1[9], h[9];
    const float R2 = 0.8f * 0.8f;
    #pragma unroll
    for (int i = 0; i < 8; i++) {
        float dx = px - OBX[i], dy = py - OBY[i];
        float bar  = dx * dx + dy * dy - R2;
        float bdot = 2.0f * dx * vc + 2.0f * dy * vs;
        G0[i] = -(-2.0f * dx * vs + 2.0f * dy * vc);
        G1[i] = -( 2.0f * dx * ct + 2.0f * dy * st);
        h[i]  = 2.0f * v * v + ssum * bdot + sprod * bar;
    }
    {
        float dxo = px - ox, dyo = py - oy;
        float so = sinf(ot), co = cosf(ot);
        float bar  = dxo * dxo + dyo * dyo - 0.25f;
        float bdot = 2.0f * dxo * (vc - ov * co) + 2.0f * dyo * (vs - ov * so);
        float Lf2  = 2.0f * (v * v + ov * ov + 2.0f * v * ov * cosf(th - ot));
        G0[8] = -(-2.0f * dxo * vs + 2.0f * dyo * vc);
        G1[8] = -( 2.0f * dxo * ct + 2.0f * dyo * st);
        h[8]  = Lf2 + ssum * bdot + sprod * bar;
    }
    float tol[9];
    #pragma unroll
    for (int i = 0; i < 9; i++) tol[i] = h[i] + 1e-6f * (1.0f + fabsf(h[i]));

    float bz0 = -p0, bz1 = -p1;
    float bobj = 3.402823466e+38f;
    auto consider = [&](float zx, float zy) {
        bool feas = true;
        #pragma unroll
        for (int k = 0; k < 9; k++)
            feas = feas && (zx * G0[k] + zy * G1[k] <= tol[k]);
        float obj = 0.5f * (zx * zx + zy * zy) + zx * p0 + zy * p1;
        if (feas && obj < bobj) { bobj = obj; bz0 = zx; bz1 = zy; }
    };
    consider(-p0, -p1);
    #pragma unroll
    for (int i = 0; i < 9; i++) {
        float gg  = G0[i] * G0[i] + G1[i] * G1[i];
        float lam = (-(G0[i] * p0 + G1[i] * p1) - h[i]) / (gg + 1e-12f);
        if (lam >= -1e-8f) consider(-p0 - lam * G0[i], -p1 - lam * G1[i]);
    }
    for (int i = 0; i < 8; i++) {
        for (int j = i + 1; j < 9; j++) {
            float det = G0[i] * G1[j] - G1[i] * G0[j];
            if (fabsf(det) > 1e-9f) {
                float zx = (h[i] * G1[j] - h[j] * G1[i]) / det;
                float zy = (G0[i] * h[j] - G0[j] * h[i]) / det;
                float r0 = -(zx + p0), r1 = -(zy + p1);
                float li = (G1[j] * r0 - G0[j] * r1) / det;
                float lj = (G0[i] * r1 - G1[i] * r0) / det;
                if (li >= -1e-8f && lj >= -1e-8f) consider(zx, zy);
            }
        }
    }
    return make_float2(bz0, bz1);
}

// ---------------------------------- prep: W21/W22 -> swizzled bf16 hi/lo image
extern "C" __global__ void bnet_prep(const float* __restrict__ W21,
                                     const float* __restrict__ W22) {
    int idx = blockIdx.x * 256 + threadIdx.x;   // 65536 = 2br * 128n * 256k
    int br = idx >> 15;
    int n  = (idx >> 8) & 127;
    int k  = idx & 255;
    const float* W = br ? W22 : W21;
    float v = W[n * 256 + k];
    __nv_bfloat16 hi = __float2bfloat16(v);
    __nv_bfloat16 lo = __float2bfloat16(v - __bfloat162float(hi));
    int c  = k >> 6;
    int kk = k & 63;
    int nc = br * 128 + n;
    uint32_t inrow = (uint32_t)(kk * 2) ^ (uint32_t)((nc & 7) << 4);  // SW128
    size_t base = (size_t)c * 65536 + (size_t)nc * 128 + inrow;
    *(__nv_bfloat16*)(BIMG + base)         = hi;
    *(__nv_bfloat16*)(BIMG + base + 32768) = lo;
}

// ------------------------------------------------------------- main kernel
extern "C" __global__ void __launch_bounds__(NTH, 2)
bnet_main(const float* __restrict__ x,   const float* __restrict__ meanv,
          const float* __restrict__ stdv,
          const float* __restrict__ W1,  const float* __restrict__ b1,
          const float* __restrict__ b21v, const float* __restrict__ W31,
          const float* __restrict__ b31v,
          const float* __restrict__ b22v, const float* __restrict__ W32,
          const float* __restrict__ b32v,
          float* __restrict__ out, int Btot)
{
    extern __shared__ unsigned char sm[];
    const uint32_t smb = smem_u32(sm);
    const int tid  = threadIdx.x;
    const int wp   = tid >> 5;
    const int lane = tid & 31;
    const int g    = lane >> 2;
    const int t    = lane & 3;
    const int rg   = wp & 1;           // rows rg*32..+32 (of 64)
    const int cg   = wp >> 1;          // cols cg*64..+64 (of 256)
    const int row0 = blockIdx.x * TB;

    float* xs   = (float*)(sm + XS_OFF);
    float* b2s  = (float*)(sm + B2_OFF);
    float* w3a  = (float*)(sm + W3A_OFF);
    float* w3b  = (float*)(sm + W3B_OFF);
    float2* red = (float2*)(sm + RED_OFF);

    // ---- B prefetch: chunk0 hi then lo (separate groups) --------------------
    auto fill_plane = [&](uint32_t dstoff, int c, int plane) {
        const unsigned char* src = BIMG + (size_t)c * 65536 + (size_t)plane * 32768;
        #pragma unroll
        for (int i = 0; i < 8; i++) {
            int idx = tid + i * NTH;
            CPASYNC16(smb + dstoff + idx * 16, src + idx * 16);
        }
    };
    fill_plane(B_HI, 0, 0); CPCOMMIT();
    fill_plane(B_LO, 0, 1); CPCOMMIT();

    // ---- small tensors + x-scale --------------------------------------------
    if (tid < 128) { b2s[tid] = b21v[tid]; b2s[128 + tid] = b22v[tid]; }
    w3a[tid] = (tid < 128) ? W31[tid] : W32[tid - 128];
    w3b[tid] = (tid < 128) ? W31[128 + tid] : W32[tid];
    for (int i = tid; i < TB * 8; i += NTH) {
        int r = i >> 3, j = i & 7;
        int gr = row0 + r;
        float v = (gr < Btot) ? x[gr * 8 + j] : 0.0f;
        xs[i] = v * stdv[j] + meanv[j];
    }
    __syncthreads();    // xs ready

    // ---- phase-1 A-chunk compute (2 units/thread, 8 rows/thread) ------------
    const int up = tid & 31;
    const int rq = tid >> 5;
    auto computeA = [&](int c, uint32_t abuf) {
        int u0 = c * 64 + up * 2;
        const float4* w4 = (const float4*)(W1 + u0 * 8);
        float4 w0a = w4[0], w0b = w4[1], w1a = w4[2], w1b = w4[3];
        float bb0 = b1[u0], bb1 = b1[u0 + 1];
        unsigned char* base = sm + abuf;
        #pragma unroll
        for (int i = 0; i < 8; i++) {
            int m = rq * 8 + i;
            float4 fa = *(const float4*)(xs + m * 8);
            float4 fb = *(const float4*)(xs + m * 8 + 4);
            float a0 = bb0, a1 = bb1;
            a0 = fmaf(fa.x, w0a.x, a0); a0 = fmaf(fa.y, w0a.y, a0);
            a0 = fmaf(fa.z, w0a.z, a0); a0 = fmaf(fa.w, w0a.w, a0);
            a0 = fmaf(fb.x, w0b.x, a0); a0 = fmaf(fb.y, w0b.y, a0);
            a0 = fmaf(fb.z, w0b.z, a0); a0 = fmaf(fb.w, w0b.w, a0);
            a1 = fmaf(fa.x, w1a.x, a1); a1 = fmaf(fa.y, w1a.y, a1);
            a1 = fmaf(fa.z, w1a.z, a1); a1 = fmaf(fa.w, w1a.w, a1);
            a1 = fmaf(fb.x, w1b.x, a1); a1 = fmaf(fb.y, w1b.y, a1);
            a1 = fmaf(fb.z, w1b.z, a1); a1 = fmaf(fb.w, w1b.w, a1);
            a0 = fmaxf(a0, 0.0f); a1 = fmaxf(a1, 0.0f);
            __nv_bfloat16 h0 = __float2bfloat16(a0);
            __nv_bfloat16 h1 = __float2bfloat16(a1);
            __nv_bfloat16 l0 = __float2bfloat16(a0 - __bfloat162float(h0));
            __nv_bfloat16 l1 = __float2bfloat16(a1 - __bfloat162float(h1));
            uint32_t hw = ((uint32_t)*(uint16_t*)&h1 << 16) | *(uint16_t*)&h0;
            uint32_t lw = ((uint32_t)*(uint16_t*)&l1 << 16) | *(uint16_t*)&l0;
            uint32_t off = (uint32_t)(m * 128 + up * 4) ^ (uint32_t)((m & 7) << 4);
            *(uint32_t*)(base + off)        = hw;
            *(uint32_t*)(base + A_LO + off) = lw;
        }
    };
    computeA(0, ABUF(0));

    // ---- fragment addressing (swizzled) --------------------------------------
    const int rowA  = rg * 32 + ((lane >> 3) & 1) * 8 + (lane & 7);
    const int halfA = (lane >> 4) * 16;
    const int xorA  = (rowA & 7) << 4;
    const int nB    = cg * 64 + ((lane >> 4) & 1) * 8 + (lane & 7);
    const int halfB = ((lane >> 3) & 1) * 16;
    const int xorB  = (lane & 7) << 4;

    float acc[2][8][4];
    #pragma unroll
    for (int mt = 0; mt < 2; mt++)
        #pragma unroll
        for (int nt = 0; nt < 8; nt++)
            #pragma unroll
            for (int e = 0; e < 4; e++) acc[mt][nt][e] = 0.0f;

    #pragma unroll
    for (int c = 0; c < 4; c++) {
        const uint32_t aB  = smb + ABUF(c & 1) + rowA * 128;
        const uint32_t bBh = smb + B_HI + nB * 128;
        const uint32_t bBl = smb + B_LO + nB * 128;

        CPWAIT(1);                 // B_HI(c) arrived
        __syncthreads();           // B_HI(c) + A(c) visible

        // ---- hi-B terms: Ahi*Bhi + Alo*Bhi ----
        #pragma unroll
        for (int k0 = 0; k0 < 64; k0 += 16) {
            const uint32_t ka = (uint32_t)((k0 * 2 + halfA) ^ xorA);
            const uint32_t kb = (uint32_t)((k0 * 2 + halfB) ^ xorB);
            uint32_t ah[2][4], al[2][4], bh[4][4];
            #pragma unroll
            for (int mt = 0; mt < 2; mt++) {
                ldsm4(ah[mt], aB + mt * (16 * 128) + ka);
                ldsm4(al[mt], aB + mt * (16 * 128) + ka + A_LO);
            }
            #pragma unroll
            for (int pr = 0; pr < 4; pr++)
                ldsm4(bh[pr], bBh + pr * (16 * 128) + kb);
            #pragma unroll
            for (int pr = 0; pr < 4; pr++)
                #pragma unroll
                for (int mt = 0; mt < 2; mt++) {
                    mma16816(acc[mt][2 * pr],     ah[mt], bh[pr][0], bh[pr][1]);
                    mma16816(acc[mt][2 * pr + 1], ah[mt], bh[pr][2], bh[pr][3]);
                }
            #pragma unroll
            for (int pr = 0; pr < 4; pr++)
                #pragma unroll
                for (int mt = 0; mt < 2; mt++) {
                    mma16816(acc[mt][2 * pr],     al[mt], bh[pr][0], bh[pr][1]);
                    mma16816(acc[mt][2 * pr + 1], al[mt], bh[pr][2], bh[pr][3]);
                }
        }
        __syncthreads();           // B_HI(c) consumed
        if (c < 3) { fill_plane(B_HI, c + 1, 0); CPCOMMIT(); }
        if (c < 3) computeA(c + 1, ABUF((c + 1) & 1));

        if (c < 3) CPWAIT(1);      // B_LO(c) done (B_HI(c+1) may pend)
        else       CPWAIT(0);
        __syncthreads();

        // ---- lo-B term: Ahi*Blo ----
        #pragma unroll
        for (int k0 = 0; k0 < 64; k0 += 16) {
            const uint32_t ka = (uint32_t)((k0 * 2 + halfA) ^ xorA);
            const uint32_t kb = (uint32_t)((k0 * 2 + halfB) ^ xorB);
            uint32_t ah[2][4], bl[4][4];
            #pragma unroll
            for (int mt = 0; mt < 2; mt++)
                ldsm4(ah[mt], aB + mt * (16 * 128) + ka);
            #pragma unroll
            for (int pr = 0; pr < 4; pr++)
                ldsm4(bl[pr], bBl + pr * (16 * 128) + kb);
            #pragma unroll
            for (int pr = 0; pr < 4; pr++)
                #pragma unroll
                for (int mt = 0; mt < 2; mt++) {
                    mma16816(acc[mt][2 * pr],     ah[mt], bl[pr][0], bl[pr][1]);
                    mma16816(acc[mt][2 * pr + 1], ah[mt], bl[pr][2], bl[pr][3]);
                }
        }
        __syncthreads();           // B_LO(c) consumed
        if (c < 3) { fill_plane(B_LO, c + 1, 1); CPCOMMIT(); }
    }

    // ---- epilogue: relu+bias, project to 2 outs, reduce -----------------------
    {
        const int branch  = cg >> 1;
        const int colbase = branch * 128 + (cg & 1) * 64;
        float y0A[2] = {0, 0}, y1A[2] = {0, 0};
        float y0B[2] = {0, 0}, y1B[2] = {0, 0};
        #pragma unroll
        for (int mt = 0; mt < 2; mt++) {
            #pragma unroll
            for (int nt = 0; nt < 8; nt++) {
                int c0 = colbase + nt * 8 + t * 2;
                float w3a0 = w3a[c0], w3a1 = w3a[c0 + 1];
                float w3b0 = w3b[c0], w3b1 = w3b[c0 + 1];
                float bb0 = b2s[c0], bb1 = b2s[c0 + 1];
                float h0 = fmaxf(acc[mt][nt][0] + bb0, 0.0f);
                float h1 = fmaxf(acc[mt][nt][1] + bb1, 0.0f);
                float h2 = fmaxf(acc[mt][nt][2] + bb0, 0.0f);
                float h3 = fmaxf(acc[mt][nt][3] + bb1, 0.0f);
                y0A[mt] = fmaf(h0, w3a0, fmaf(h1, w3a1, y0A[mt]));
                y1A[mt] = fmaf(h0, w3b0, fmaf(h1, w3b1, y1A[mt]));
                y0B[mt] = fmaf(h2, w3a0, fmaf(h3, w3a1, y0B[mt]));
                y1B[mt] = fmaf(h2, w3b0, fmaf(h3, w3b1, y1B[mt]));
            }
        }
        #pragma unroll
        for (int mt = 0; mt < 2; mt++) {
            #pragma unroll
            for (int msk = 1; msk <= 2; msk <<= 1) {
                y0A[mt] += __shfl_xor_sync(0xFFFFFFFFu, y0A[mt], msk);
                y1A[mt] += __shfl_xor_sync(0xFFFFFFFFu, y1A[mt], msk);
                y0B[mt] += __shfl_xor_sync(0xFFFFFFFFu, y0B[mt], msk);
                y1B[mt] += __shfl_xor_sync(0xFFFFFFFFu, y1B[mt], msk);
            }
        }
        if (t == 0) {
            #pragma unroll
            for (int mt = 0; mt < 2; mt++) {
                int rA = rg * 32 + mt * 16 + g;
                red[cg * TB + rA]     = make_float2(y0A[mt], y1A[mt]);
                red[cg * TB + rA + 8] = make_float2(y0B[mt], y1B[mt]);
            }
        }
    }
    __syncthreads();

    // ---- final combine + QP (64 rows; co-resident CTA overlaps this tail) ----
    if (tid < TB) {
        const int gr = row0 + tid;
        if (gr < Btot) {
            float2 a0 = red[tid];
            float2 a1 = red[TB + tid];
            float2 c0 = red[2 * TB + tid];
            float2 c1 = red[3 * TB + tid];
            float p0 = a0.x + a1.x + b31v[0];
            float p1 = a0.y + a1.y + b31v[1];
            float q0 = c0.x + c1.x + b32v[0];
            float q1 = c0.y + c1.y + b32v[1];
            float s0 = 4.0f / (1.0f + expf(-q0));
            float s1 = 4.0f / (1.0f + expf(-q1));
            float2 z = qp_solve(&xs[tid * 8], p0, p1, s0, s1);
            *(float2*)(out + gr * 2) = z;
        }
    }
}

// ---------------------------------------------------------------- launcher
extern "C" void kernel_launch(void* const* d_in, const int* in_sizes, int n_in,
                              void* d_out, int out_size)
{
    const float* x     = (const float*)d_in[0];
    const float* meanv = (const float*)d_in[1];
    const float* stdv  = (const float*)d_in[2];
    const float* W1    = (const float*)d_in[3];
    const float* b1    = (const float*)d_in[4];
    const float* W21   = (const float*)d_in[5];
    const float* b21   = (const float*)d_in[6];
    const float* W31   = (const float*)d_in[7];
    const float* b31   = (const float*)d_in[8];
    const float* W22   = (const float*)d_in[9];
    const float* b22   = (const float*)d_in[10];
    const float* W32   = (const float*)d_in[11];
    const float* b32   = (const float*)d_in[12];
    float* out = (float*)d_out;

    const int Btot = in_sizes[0] / 8;
    const int grid = (Btot + TB - 1) / TB;

    bnet_prep<<<256, 256>>>(W21, W22);

    cudaFuncSetAttribute(bnet_main, cudaFuncAttributeMaxDynamicSharedMemorySize,
                         SMEM_TOTAL);
    bnet_main<<<grid, NTH, SMEM_TOTAL>>>(x, meanv, stdv, W1, b1,
                                         b21, W31, b31, b22, W32, b32,
                                         out, Btot);
}

// round 7
// speedup vs baseline: 1.2618x; 1.0235x over previous
#include <cuda_runtime.h>
#include <cuda_bf16.h>
#include <cstdint>

// ============================================================================
// BarrierNet — HMMA bf16 hi/lo (~fp32), 256thr/64row CTAs, 2 CTAs/SM,
// double-buffered A, single-stage merged-plane cp.async B (1 wait + 2 syncs
// per chunk), fused epilogue + closed-form QP.
// ============================================================================

#define NTH        256
#define TB         64

// smem byte offsets
#define ABUF(i)    ((i) * 16384)      // 2 x (hi 8192 + lo 8192)
#define A_LO       8192
#define B_OFF      32768              // 65536 B chunk: hi at +0, lo at +32768
#define B_LOPL     32768
#define XS_OFF     98304              // 64*8 f32 = 2048
#define B2_OFF     100352             // 256 f32
#define W3A_OFF    101376
#define W3B_OFF    102400
#define RED_OFF    103424             // 4 x 64 float2 = 2048
#define SMEM_TOTAL 105472

// prep image: [chunk4][plane2(hi,lo)][nc256][128B swizzled]  (65536 B / chunk)
__device__ __align__(16) unsigned char BIMG[262144];

__constant__ float OBX[8] = {
    10.0f, 7.0710678118654755f, 6.123233995736766e-16f, -7.0710678118654755f,
    -10.0f, -7.0710678118654755f, -1.8369701987210297e-15f, 7.0710678118654755f };
__constant__ float OBY[8] = {
    0.0f, 7.0710678118654755f, 10.0f, 7.0710678118654755f,
    1.2246467991473532e-15f, -7.0710678118654755f, -10.0f, -7.0710678118654755f };

// ---------------------------------------------------------------- asm helpers
__device__ __forceinline__ uint32_t smem_u32(const void* p) {
    uint32_t a;
    asm("{ .reg .u64 t; cvta.to.shared.u64 t, %1; cvt.u32.u64 %0, t; }"
        : "=r"(a) : "l"(p));
    return a;
}
__device__ __forceinline__ void mma16816(float* d, const uint32_t* a,
                                         uint32_t b0, uint32_t b1) {
    asm volatile(
        "mma.sync.aligned.m16n8k16.row.col.f32.bf16.bf16.f32 "
        "{%0,%1,%2,%3}, {%4,%5,%6,%7}, {%8,%9}, {%0,%1,%2,%3};"
        : "+f"(d[0]), "+f"(d[1]), "+f"(d[2]), "+f"(d[3])
        : "r"(a[0]), "r"(a[1]), "r"(a[2]), "r"(a[3]), "r"(b0), "r"(b1));
}
__device__ __forceinline__ void ldsm4(uint32_t* r, uint32_t addr) {
    asm volatile("ldmatrix.sync.aligned.m8n8.x4.shared.b16 {%0,%1,%2,%3}, [%4];"
                 : "=r"(r[0]), "=r"(r[1]), "=r"(r[2]), "=r"(r[3]) : "r"(addr));
}
#define CPASYNC16(dst, src) \
    asm volatile("cp.async.cg.shared.global [%0], [%1], 16;" \
                 :: "r"(dst), "l"(src))
#define CPCOMMIT() asm volatile("cp.async.commit_group;")
#define CPWAIT(n)  asm volatile("cp.async.wait_group %0;" :: "n"(n))

// ------------------------------------------------------------ QP (validated)
__device__ __forceinline__ float2 qp_solve(const float* f, float p0, float p1,
                                           float s0, float s1) {
    float px = f[0], py = f[1], th = f[2], v  = f[3];
    float ox = f[4], oy = f[5], ot = f[6], ov = f[7];
    float st = sinf(th), ct = cosf(th);
    float vs = v * st,  vc = v * ct;
    float ssum = s0 + s1, sprod = s0 * s1;

    float G0[9], G1[9], h[9];
    const float R2 = 0.8f * 0.8f;
    #pragma unroll
    for (int i = 0; i < 8; i++) {
        float dx = px - OBX[i], dy = py - OBY[i];
        float bar  = dx * dx + dy * dy - R2;
        float bdot = 2.0f * dx * vc + 2.0f * dy * vs;
        G0[i] = -(-2.0f * dx * vs + 2.0f * dy * vc);
        G1[i] = -( 2.0f * dx * ct + 2.0f * dy * st);
        h[i]  = 2.0f * v * v + ssum * bdot + sprod * bar;
    }
    {
        float dxo = px - ox, dyo = py - oy;
        float so = sinf(ot), co = cosf(ot);
        float bar  = dxo * dxo + dyo * dyo - 0.25f;
        float bdot = 2.0f * dxo * (vc - ov * co) + 2.0f * dyo * (vs - ov * so);
        float Lf2  = 2.0f * (v * v + ov * ov + 2.0f * v * ov * cosf(th - ot));
        G0[8] = -(-2.0f * dxo * vs + 2.0f * dyo * vc);
        G1[8] = -( 2.0f * dxo * ct + 2.0f * dyo * st);
        h[8]  = Lf2 + ssum * bdot + sprod * bar;
    }
    float tol[9];
    #pragma unroll
    for (int i = 0; i < 9; i++) tol[i] = h[i] + 1e-6f * (1.0f + fabsf(h[i]));

    float bz0 = -p0, bz1 = -p1;
    float bobj = 3.402823466e+38f;
    auto consider = [&](float zx, float zy) {
        bool feas = true;
        #pragma unroll
        for (int k = 0; k < 9; k++)
            feas = feas && (zx * G0[k] + zy * G1[k] <= tol[k]);
        float obj = 0.5f * (zx * zx + zy * zy) + zx * p0 + zy * p1;
        if (feas && obj < bobj) { bobj = obj; bz0 = zx; bz1 = zy; }
    };
    consider(-p0, -p1);
    #pragma unroll
    for (int i = 0; i < 9; i++) {
        float gg  = G0[i] * G0[i] + G1[i] * G1[i];
        float lam = (-(G0[i] * p0 + G1[i] * p1) - h[i]) / (gg + 1e-12f);
        if (lam >= -1e-8f) consider(-p0 - lam * G0[i], -p1 - lam * G1[i]);
    }
    for (int i = 0; i < 8; i++) {
        for (int j = i + 1; j < 9; j++) {
            float det = G0[i] * G1[j] - G1[i] * G0[j];
            if (fabsf(det) > 1e-9f) {
                float zx = (h[i] * G1[j] - h[j] * G1[i]) / det;
                float zy = (G0[i] * h[j] - G0[j] * h[i]) / det;
                float r0 = -(zx + p0), r1 = -(zy + p1);
                float li = (G1[j] * r0 - G0[j] * r1) / det;
                float lj = (G0[i] * r1 - G1[i] * r0) / det;
                if (li >= -1e-8f && lj >= -1e-8f) consider(zx, zy);
            }
        }
    }
    return make_float2(bz0, bz1);
}

// ---------------------------------- prep: W21/W22 -> swizzled bf16 hi/lo image
extern "C" __global__ void bnet_prep(const float* __restrict__ W21,
                                     const float* __restrict__ W22) {
    int idx = blockIdx.x * 256 + threadIdx.x;   // 65536 = 2br * 128n * 256k
    int br = idx >> 15;
    int n  = (idx >> 8) & 127;
    int k  = idx & 255;
    const float* W = br ? W22 : W21;
    float v = W[n * 256 + k];
    __nv_bfloat16 hi = __float2bfloat16(v);
    __nv_bfloat16 lo = __float2bfloat16(v - __bfloat162float(hi));
    int c  = k >> 6;
    int kk = k & 63;
    int nc = br * 128 + n;
    uint32_t inrow = (uint32_t)(kk * 2) ^ (uint32_t)((nc & 7) << 4);  // SW128
    size_t base = (size_t)c * 65536 + (size_t)nc * 128 + inrow;
    *(__nv_bfloat16*)(BIMG + base)         = hi;
    *(__nv_bfloat16*)(BIMG + base + 32768) = lo;
}

// ------------------------------------------------------------- main kernel
extern "C" __global__ void __launch_bounds__(NTH, 2)
bnet_main(const float* __restrict__ x,   const float* __restrict__ meanv,
          const float* __restrict__ stdv,
          const float* __restrict__ W1,  const float* __restrict__ b1,
          const float* __restrict__ b21v, const float* __restrict__ W31,
          const float* __restrict__ b31v,
          const float* __restrict__ b22v, const float* __restrict__ W32,
          const float* __restrict__ b32v,
          float* __restrict__ out, int Btot)
{
    extern __shared__ unsigned char sm[];
    const uint32_t smb = smem_u32(sm);
    const int tid  = threadIdx.x;
    const int wp   = tid >> 5;
    const int lane = tid & 31;
    const int g    = lane >> 2;
    const int t    = lane & 3;
    const int rg   = wp & 1;           // rows rg*32..+32 (of 64)
    const int cg   = wp >> 1;          // cols cg*64..+64 (of 256)
    const int row0 = blockIdx.x * TB;

    float* xs   = (float*)(sm + XS_OFF);
    float* b2s  = (float*)(sm + B2_OFF);
    float* w3a  = (float*)(sm + W3A_OFF);
    float* w3b  = (float*)(sm + W3B_OFF);
    float2* red = (float2*)(sm + RED_OFF);

    // ---- B chunk prefetch (both planes, one group, 64 KB) -------------------
    auto fill_chunk = [&](int c) {
        const unsigned char* src = BIMG + (size_t)c * 65536;
        #pragma unroll
        for (int i = 0; i < 16; i++) {
            int idx = tid + i * NTH;
            CPASYNC16(smb + B_OFF + idx * 16, src + idx * 16);
        }
    };
    fill_chunk(0); CPCOMMIT();

    // ---- small tensors + x-scale --------------------------------------------
    if (tid < 128) { b2s[tid] = b21v[tid]; b2s[128 + tid] = b22v[tid]; }
    w3a[tid] = (tid < 128) ? W31[tid] : W32[tid - 128];
    w3b[tid] = (tid < 128) ? W31[128 + tid] : W32[tid];
    for (int i = tid; i < TB * 8; i += NTH) {
        int r = i >> 3, j = i & 7;
        int gr = row0 + r;
        float v = (gr < Btot) ? x[gr * 8 + j] : 0.0f;
        xs[i] = v * stdv[j] + meanv[j];
    }
    __syncthreads();    // xs ready

    // ---- phase-1 A-chunk compute (2 units/thread, 8 rows/thread) ------------
    const int up = tid & 31;
    const int rq = tid >> 5;
    auto computeA = [&](int c, uint32_t abuf) {
        int u0 = c * 64 + up * 2;
        const float4* w4 = (const float4*)(W1 + u0 * 8);
        float4 w0a = w4[0], w0b = w4[1], w1a = w4[2], w1b = w4[3];
        float bb0 = b1[u0], bb1 = b1[u0 + 1];
        unsigned char* base = sm + abuf;
        #pragma unroll
        for (int i = 0; i < 8; i++) {
            int m = rq * 8 + i;
            float4 fa = *(const float4*)(xs + m * 8);
            float4 fb = *(const float4*)(xs + m * 8 + 4);
            float a0 = bb0, a1 = bb1;
            a0 = fmaf(fa.x, w0a.x, a0); a0 = fmaf(fa.y, w0a.y, a0);
            a0 = fmaf(fa.z, w0a.z, a0); a0 = fmaf(fa.w, w0a.w, a0);
            a0 = fmaf(fb.x, w0b.x, a0); a0 = fmaf(fb.y, w0b.y, a0);
            a0 = fmaf(fb.z, w0b.z, a0); a0 = fmaf(fb.w, w0b.w, a0);
            a1 = fmaf(fa.x, w1a.x, a1); a1 = fmaf(fa.y, w1a.y, a1);
            a1 = fmaf(fa.z, w1a.z, a1); a1 = fmaf(fa.w, w1a.w, a1);
            a1 = fmaf(fb.x, w1b.x, a1); a1 = fmaf(fb.y, w1b.y, a1);
            a1 = fmaf(fb.z, w1b.z, a1); a1 = fmaf(fb.w, w1b.w, a1);
            a0 = fmaxf(a0, 0.0f); a1 = fmaxf(a1, 0.0f);
            __nv_bfloat16 h0 = __float2bfloat16(a0);
            __nv_bfloat16 h1 = __float2bfloat16(a1);
            __nv_bfloat16 l0 = __float2bfloat16(a0 - __bfloat162float(h0));
            __nv_bfloat16 l1 = __float2bfloat16(a1 - __bfloat162float(h1));
            uint32_t hw = ((uint32_t)*(uint16_t*)&h1 << 16) | *(uint16_t*)&h0;
            uint32_t lw = ((uint32_t)*(uint16_t*)&l1 << 16) | *(uint16_t*)&l0;
            uint32_t off = (uint32_t)(m * 128 + up * 4) ^ (uint32_t)((m & 7) << 4);
            *(uint32_t*)(base + off)        = hw;
            *(uint32_t*)(base + A_LO + off) = lw;
        }
    };
    computeA(0, ABUF(0));

    // ---- fragment addressing (swizzled) --------------------------------------
    const int rowA  = rg * 32 + ((lane >> 3) & 1) * 8 + (lane & 7);
    const int halfA = (lane >> 4) * 16;
    const int xorA  = (rowA & 7) << 4;
    const int nB    = cg * 64 + ((lane >> 4) & 1) * 8 + (lane & 7);
    const int halfB = ((lane >> 3) & 1) * 16;
    const int xorB  = (lane & 7) << 4;

    float acc[2][8][4];
    #pragma unroll
    for (int mt = 0; mt < 2; mt++)
        #pragma unroll
        for (int nt = 0; nt < 8; nt++)
            #pragma unroll
            for (int e = 0; e < 4; e++) acc[mt][nt][e] = 0.0f;

    #pragma unroll
    for (int c = 0; c < 4; c++) {
        const uint32_t aB = smb + ABUF(c & 1) + rowA * 128;
        const uint32_t bB = smb + B_OFF + nB * 128;

        CPWAIT(0);                 // B(c) (both planes) arrived
        __syncthreads();           // B(c) + A(c) visible to all warps

        // ---- single uninterrupted MMA block: 48 LDSM + 192 HMMA ----
        #pragma unroll
        for (int k0 = 0; k0 < 64; k0 += 16) {
            const uint32_t ka = (uint32_t)((k0 * 2 + halfA) ^ xorA);
            const uint32_t kb = (uint32_t)((k0 * 2 + halfB) ^ xorB);
            uint32_t ah[2][4], al[2][4], bh[4][4];
            #pragma unroll
            for (int mt = 0; mt < 2; mt++) {
                ldsm4(ah[mt], aB + mt * (16 * 128) + ka);
                ldsm4(al[mt], aB + mt * (16 * 128) + ka + A_LO);
            }
            #pragma unroll
            for (int pr = 0; pr < 4; pr++)
                ldsm4(bh[pr], bB + pr * (16 * 128) + kb);
            // hi-B terms: Ahi*Bhi + Alo*Bhi
            #pragma unroll
            for (int pr = 0; pr < 4; pr++)
                #pragma unroll
                for (int mt = 0; mt < 2; mt++) {
                    mma16816(acc[mt][2 * pr],     ah[mt], bh[pr][0], bh[pr][1]);
                    mma16816(acc[mt][2 * pr + 1], ah[mt], bh[pr][2], bh[pr][3]);
                    mma16816(acc[mt][2 * pr],     al[mt], bh[pr][0], bh[pr][1]);
                    mma16816(acc[mt][2 * pr + 1], al[mt], bh[pr][2], bh[pr][3]);
                }
            // lo-B term: Ahi*Blo (bl loaded late, reuses bh registers)
            uint32_t bl[4][4];
            #pragma unroll
            for (int pr = 0; pr < 4; pr++)
                ldsm4(bl[pr], bB + pr * (16 * 128) + kb + B_LOPL);
            #pragma unroll
            for (int pr = 0; pr < 4; pr++)
                #pragma unroll
                for (int mt = 0; mt < 2; mt++) {
                    mma16816(acc[mt][2 * pr],     ah[mt], bl[pr][0], bl[pr][1]);
                    mma16816(acc[mt][2 * pr + 1], ah[mt], bl[pr][2], bl[pr][3]);
                }
        }
        __syncthreads();           // B(c) consumed by all warps
        if (c < 3) {
            fill_chunk(c + 1); CPCOMMIT();       // copy streams under FMA work
            computeA(c + 1, ABUF((c + 1) & 1));
        }
    }

    // ---- epilogue: relu+bias, project to 2 outs, reduce -----------------------
    {
        const int branch  = cg >> 1;
        const int colbase = branch * 128 + (cg & 1) * 64;
        float y0A[2] = {0, 0}, y1A[2] = {0, 0};
        float y0B[2] = {0, 0}, y1B[2] = {0, 0};
        #pragma unroll
        for (int mt = 0; mt < 2; mt++) {
            #pragma unroll
            for (int nt = 0; nt < 8; nt++) {
                int c0 = colbase + nt * 8 + t * 2;
                float w3a0 = w3a[c0], w3a1 = w3a[c0 + 1];
                float w3b0 = w3b[c0], w3b1 = w3b[c0 + 1];
                float bb0 = b2s[c0], bb1 = b2s[c0 + 1];
                float h0 = fmaxf(acc[mt][nt][0] + bb0, 0.0f);
                float h1 = fmaxf(acc[mt][nt][1] + bb1, 0.0f);
                float h2 = fmaxf(acc[mt][nt][2] + bb0, 0.0f);
                float h3 = fmaxf(acc[mt][nt][3] + bb1, 0.0f);
                y0A[mt] = fmaf(h0, w3a0, fmaf(h1, w3a1, y0A[mt]));
                y1A[mt] = fmaf(h0, w3b0, fmaf(h1, w3b1, y1A[mt]));
                y0B[mt] = fmaf(h2, w3a0, fmaf(h3, w3a1, y0B[mt]));
                y1B[mt] = fmaf(h2, w3b0, fmaf(h3, w3b1, y1B[mt]));
            }
        }
        #pragma unroll
        for (int mt = 0; mt < 2; mt++) {
            #pragma unroll
            for (int msk = 1; msk <= 2; msk <<= 1) {
                y0A[mt] += __shfl_xor_sync(0xFFFFFFFFu, y0A[mt], msk);
                y1A[mt] += __shfl_xor_sync(0xFFFFFFFFu, y1A[mt], msk);
                y0B[mt] += __shfl_xor_sync(0xFFFFFFFFu, y0B[mt], msk);
                y1B[mt] += __shfl_xor_sync(0xFFFFFFFFu, y1B[mt], msk);
            }
        }
        if (t == 0) {
            #pragma unroll
            for (int mt = 0; mt < 2; mt++) {
                int rA = rg * 32 + mt * 16 + g;
                red[cg * TB + rA]     = make_float2(y0A[mt], y1A[mt]);
                red[cg * TB + rA + 8] = make_float2(y0B[mt], y1B[mt]);
            }
        }
    }
    __syncthreads();

    // ---- final combine + QP (64 rows; co-resident CTA overlaps this tail) ----
    if (tid < TB) {
        const int gr = row0 + tid;
        if (gr < Btot) {
            float2 a0 = red[tid];
            float2 a1 = red[TB + tid];
            float2 c0 = red[2 * TB + tid];
            float2 c1 = red[3 * TB + tid];
            float p0 = a0.x + a1.x + b31v[0];
            float p1 = a0.y + a1.y + b31v[1];
            float q0 = c0.x + c1.x + b32v[0];
            float q1 = c0.y + c1.y + b32v[1];
            float s0 = 4.0f / (1.0f + expf(-q0));
            float s1 = 4.0f / (1.0f + expf(-q1));
            float2 z = qp_solve(&xs[tid * 8], p0, p1, s0, s1);
            *(float2*)(out + gr * 2) = z;
        }
    }
}

// ---------------------------------------------------------------- launcher
extern "C" void kernel_launch(void* const* d_in, const int* in_sizes, int n_in,
                              void* d_out, int out_size)
{
    const float* x     = (const float*)d_in[0];
    const float* meanv = (const float*)d_in[1];
    const float* stdv  = (const float*)d_in[2];
    const float* W1    = (const float*)d_in[3];
    const float* b1    = (const float*)d_in[4];
    const float* W21   = (const float*)d_in[5];
    const float* b21   = (const float*)d_in[6];
    const float* W31   = (const float*)d_in[7];
    const float* b31   = (const float*)d_in[8];
    const float* W22   = (const float*)d_in[9];
    const float* b22   = (const float*)d_in[10];
    const float* W32   = (const float*)d_in[11];
    const float* b32   = (const float*)d_in[12];
    float* out = (float*)d_out;

    const int Btot = in_sizes[0] / 8;
    const int grid = (Btot + TB - 1) / TB;

    bnet_prep<<<256, 256>>>(W21, W22);

    cudaFuncSetAttribute(bnet_main, cudaFuncAttributeMaxDynamicSharedMemorySize,
                         SMEM_TOTAL);
    bnet_main<<<grid, NTH, SMEM_TOTAL>>>(x, meanv, stdv, W1, b1,
                                         b21, W31, b31, b22, W32, b32,
                                         out, Btot);
}